// round 6
// baseline (speedup 1.0000x reference)
#include <cuda_runtime.h>
#include <cuda_fp16.h>
#include <cstdint>

#define HH 256
#define WW 256

__device__ __forceinline__ uint32_t smem_u32(const void* p) {
    uint32_t a;
    asm("{ .reg .u64 t; cvta.to.shared.u64 t, %1; cvt.u32.u64 %0, t; }" : "=r"(a) : "l"(p));
    return a;
}

// ============================ weight prep =====================================
// g_W3[chunk][tap][oc][psi] : half2 = (W[ic0+2p], W[ic0+2p+1]), psi(p)=(p&3)*2+(p>>2)
// LDS.64 at u32 offset 2*tig yields pairs {tig, tig+4} = (b0, b1) of m16n8k16.
__device__ uint32_t g_W3[4 * 9 * 64 * 8];

__global__ void prep_weights(const float* __restrict__ Wt) {
    int i = blockIdx.x * 256 + threadIdx.x;   // 18432 total
    if (i >= 4 * 9 * 64 * 8) return;
    int q     = i & 7;
    int oc    = (i >> 3) & 63;
    int tap   = (i >> 9) % 9;
    int chunk = i / (512 * 9);
    int p     = (q >> 1) + (q & 1) * 4;       // inverse psi
    int kh    = tap / 3;
    int kw    = tap % 3;
    int ic    = chunk * 16 + 2 * p;
    float w0 = Wt[((oc * 64 + ic) * 3 + kh) * 3 + kw];
    float w1 = Wt[((oc * 64 + ic + 1) * 3 + kh) * 3 + kw];
    __half2 hv = __floats2half2_rn(w0, w1);
    g_W3[i] = *(uint32_t*)&hv;
}

// SMEM (u32): sIn[4 rows][132 px][12] = 6336, sW[9][64][8] = 4608, sB[64]
#define SIN_U32 (4 * 132 * 12)
#define SW_U32  (9 * 64 * 8)
#define SMEM_BYTES ((SIN_U32 + SW_U32 + 64) * 4)

__global__ __launch_bounds__(256, 2)
void conv_f16_mma_kernel(const float* __restrict__ x,
                         const float* __restrict__ bias,
                         float* __restrict__ out)
{
    extern __shared__ uint32_t sm[];
    uint32_t* sIn = sm;                   // [r][c][p]  (p: 8 data u32 + 4 pad)
    uint32_t* sW  = sm + SIN_U32;         // [tap][oc][psi]
    float*    sB  = (float*)(sm + SIN_U32 + SW_U32);
    const uint32_t sInAddr = smem_u32(sIn);

    const int tid  = threadIdx.x;
    const int lane = tid & 31;
    const int wid  = tid >> 5;
    const int g    = lane >> 2;
    const int tig  = lane & 3;
    const int w0   = blockIdx.x * 128;    // w-half
    const int h0   = blockIdx.y * 2;      // h-pair
    const int n    = blockIdx.z;

    // warp tiling: r_out = wid>>2 (output row), colhalf = (wid>>1)&1, ochalf = wid&1
    const int r_out = wid >> 2;
    const int cb64  = 64 * ((wid >> 1) & 1);
    const int oc0   = 32 * (wid & 1);

    // ldmatrix lane address pieces
    const int m_lane = (lane & 7) + 8 * ((lane >> 3) & 1);
    const uint32_t khalf_b = (lane >> 4) * 16;   // bytes: k-half select

    if (tid < 64) sB[tid] = bias[tid];

    float c[4][4][4];
    #pragma unroll
    for (int mt = 0; mt < 4; ++mt)
        #pragma unroll
        for (int nt = 0; nt < 4; ++nt)
            #pragma unroll
            for (int r = 0; r < 4; ++r) c[mt][nt][r] = 0.0f;

    for (int chunk = 0; chunk < 4; ++chunk) {
        const int ic0 = chunk * 16;
        if (chunk) __syncthreads();

        // ---- stage input: 4 rows x 8 ic-pairs x 130 cols ----
        for (int i = tid; i < 4 * 8 * 130; i += 256) {
            int col = i % 130;            // coalesced LDG across lanes
            int t2  = i / 130;
            int p   = t2 & 7;
            int r   = t2 >> 3;
            int gh  = h0 - 1 + r;
            int gw  = w0 - 1 + col;
            float v0 = 0.0f, v1 = 0.0f;
            if ((unsigned)gh < 256u && (unsigned)gw < 256u) {
                const float* base = x + (((size_t)n * 64 + ic0 + 2 * p) * 256 + gh) * 256 + gw;
                v0 = base[0];
                v1 = base[256 * 256];
            }
            __half2 hv = __floats2half2_rn(v0, v1);
            sIn[r * (132 * 12) + col * 12 + p] = *(uint32_t*)&hv;
        }
        // ---- stage weights: vector copy of pre-packed chunk ----
        {
            const uint4* src = (const uint4*)(g_W3 + chunk * SW_U32);
            uint4* dst = (uint4*)sW;
            for (int i = tid; i < SW_U32 / 4; i += 256)
                dst[i] = src[i];
        }
        __syncthreads();

        // ---- compute: 9 taps; A via ldmatrix.x4, B via LDS.64 ----
        #pragma unroll
        for (int kh = 0; kh < 3; ++kh) {
            const uint32_t rowA = sInAddr + (uint32_t)((r_out + kh) * (132 * 12)) * 4u;
            #pragma unroll
            for (int kw = 0; kw < 3; ++kw) {
                const uint32_t* wB = sW + (kh * 3 + kw) * (64 * 8);
                uint32_t b[4][2];
                #pragma unroll
                for (int nt = 0; nt < 4; ++nt) {
                    const uint2 bv = *(const uint2*)(wB + (oc0 + nt * 8 + g) * 8 + 2 * tig);
                    b[nt][0] = bv.x;
                    b[nt][1] = bv.y;
                }
                const uint32_t aBase = rowA + (uint32_t)((cb64 + m_lane + kw) * 12) * 4u + khalf_b;
                #pragma unroll
                for (int mt = 0; mt < 4; ++mt) {
                    uint32_t a0, a1, a2, a3;
                    asm volatile(
                        "ldmatrix.sync.aligned.m8n8.x4.shared.b16 {%0,%1,%2,%3}, [%4];"
                        : "=r"(a0), "=r"(a1), "=r"(a2), "=r"(a3)
                        : "r"(aBase + (uint32_t)(mt * 16 * 12) * 4u));
                    #pragma unroll
                    for (int nt = 0; nt < 4; ++nt)
                        asm volatile(
                            "mma.sync.aligned.m16n8k16.row.col.f32.f16.f16.f32 "
                            "{%0,%1,%2,%3}, {%4,%5,%6,%7}, {%8,%9}, {%0,%1,%2,%3};"
                            : "+f"(c[mt][nt][0]), "+f"(c[mt][nt][1]),
                              "+f"(c[mt][nt][2]), "+f"(c[mt][nt][3])
                            : "r"(a0), "r"(a1), "r"(a2), "r"(a3),
                              "r"(b[nt][0]), "r"(b[nt][1]));
                }
            }
        }
    }

    // ---- epilogue: bias + store ----
    const int h = h0 + r_out;
    #pragma unroll
    for (int mt = 0; mt < 4; ++mt) {
        const int px = w0 + cb64 + mt * 16 + g;
        #pragma unroll
        for (int nt = 0; nt < 4; ++nt) {
            const int oc = oc0 + nt * 8 + 2 * tig;
            const size_t b0 = (((size_t)n * 64 + oc) * 256 + h) * 256;
            const size_t b1 = (((size_t)n * 64 + oc + 1) * 256 + h) * 256;
            out[b0 + px]     = c[mt][nt][0] + sB[oc];
            out[b1 + px]     = c[mt][nt][1] + sB[oc + 1];
            out[b0 + px + 8] = c[mt][nt][2] + sB[oc];
            out[b1 + px + 8] = c[mt][nt][3] + sB[oc + 1];
        }
    }
}

extern "C" void kernel_launch(void* const* d_in, const int* in_sizes, int n_in,
                              void* d_out, int out_size)
{
    const float* x  = (const float*)d_in[0];
    const float* Wt = (const float*)d_in[1];
    const float* b  = (const float*)d_in[2];
    float* out = (float*)d_out;

    cudaFuncSetAttribute(conv_f16_mma_kernel,
                         cudaFuncAttributeMaxDynamicSharedMemorySize, SMEM_BYTES);

    prep_weights<<<72, 256>>>(Wt);

    dim3 grid(2, 128, 16);   // (w-half, h-pair, n): 4096 CTAs, 2x128 px x 64 oc
    conv_f16_mma_kernel<<<grid, 256, SMEM_BYTES>>>(x, b, out);
}

// round 7
// speedup vs baseline: 1.2708x; 1.2708x over previous
#include <cuda_runtime.h>
#include <cuda_fp16.h>
#include <cstdint>

// ============================ weight prep =====================================
// g_W3[chunk][tap][oc][psi] : half2 = (W[ic0+2p], W[ic0+2p+1]), psi(p)=(p&3)*2+(p>>2)
// LDG.64 at u32 offset 2*tig yields pairs {tig, tig+4} = (b0, b1) of m16n8k16.
__device__ uint32_t g_W3[4 * 9 * 64 * 8];

__global__ void prep_weights(const float* __restrict__ Wt) {
    int i = blockIdx.x * 256 + threadIdx.x;   // 18432 total
    if (i >= 4 * 9 * 64 * 8) return;
    int q     = i & 7;
    int oc    = (i >> 3) & 63;
    int tap   = (i >> 9) % 9;
    int chunk = i / (512 * 9);
    int p     = (q >> 1) + (q & 1) * 4;       // inverse psi
    int kh    = tap / 3;
    int kw    = tap % 3;
    int ic    = chunk * 16 + 2 * p;
    float w0 = Wt[((oc * 64 + ic) * 3 + kh) * 3 + kw];
    float w1 = Wt[((oc * 64 + ic + 1) * 3 + kh) * 3 + kw];
    __half2 hv = __floats2half2_rn(w0, w1);
    g_W3[i] = *(uint32_t*)&hv;
}

// SMEM (u32): sIn[2 buf][4 r][8 p][136] + bias
#define COLS 130
#define CSTR 136
#define SIN_BUF (4 * 8 * CSTR)              // 4352 u32 per buffer
#define SMEM_BYTES ((2 * SIN_BUF + 64) * 4) // ~35 KB

__global__ __launch_bounds__(256, 2)
void conv_f16_mma_kernel(const float* __restrict__ x,
                         const float* __restrict__ bias,
                         float* __restrict__ out)
{
    extern __shared__ uint32_t sm[];
    uint32_t* sIn = sm;                         // [buf][r][p][col]
    float*    sB  = (float*)(sm + 2 * SIN_BUF);

    const int tid  = threadIdx.x;
    const int lane = tid & 31;
    const int wid  = tid >> 5;
    const int g    = lane >> 2;
    const int tig  = lane & 3;
    const int w0   = blockIdx.x * 128;          // w-half
    const int h0   = blockIdx.y * 2;            // h-pair
    const int n    = blockIdx.z;

    // 8 warps: r_out(2) x col-half(2) x oc-half(2); each warp 64 px x 32 oc
    const int r_out = wid >> 2;
    const int cb64  = 64 * ((wid >> 1) & 1);
    const int oc0   = 32 * (wid & 1);

    if (tid < 64) sB[tid] = bias[tid];

    float c[4][4][4];
    #pragma unroll
    for (int mt = 0; mt < 4; ++mt)
        #pragma unroll
        for (int nt = 0; nt < 4; ++nt)
            #pragma unroll
            for (int r = 0; r < 4; ++r) c[mt][nt][r] = 0.0f;

    // ---- staging helper: 4 rows x 8 ic-pairs x 130 cols as half2 ----
    auto stage = [&](int chunk, uint32_t* dst) {
        const int ic0 = chunk * 16;
        for (int i = tid; i < 4 * 8 * COLS; i += 256) {
            int col = i % COLS;                  // coalesced across lanes
            int t2  = i / COLS;
            int p   = t2 & 7;
            int r   = t2 >> 3;
            int gh  = h0 - 1 + r;
            int gw  = w0 - 1 + col;
            float v0 = 0.0f, v1 = 0.0f;
            if ((unsigned)gh < 256u && (unsigned)gw < 256u) {
                const float* base = x + (((size_t)n * 64 + ic0 + 2 * p) * 256 + gh) * 256 + gw;
                v0 = __ldg(base);
                v1 = __ldg(base + 256 * 256);
            }
            __half2 hv = __floats2half2_rn(v0, v1);
            dst[r * (8 * CSTR) + p * CSTR + col] = *(uint32_t*)&hv;
        }
    };

    stage(0, sIn);
    __syncthreads();

    for (int chunk = 0; chunk < 4; ++chunk) {
        const uint32_t* buf = sIn + (chunk & 1) * SIN_BUF;
        const uint32_t* wG  = g_W3 + chunk * (9 * 64 * 8);

        // ---- compute: 9 taps x (4 mt x 4 nt) m16n8k16 ----
        #pragma unroll
        for (int kh = 0; kh < 3; ++kh) {
            const uint32_t* rowA = buf + (r_out + kh) * (8 * CSTR);
            #pragma unroll
            for (int kw = 0; kw < 3; ++kw) {
                const uint32_t* wB = wG + (kh * 3 + kw) * (64 * 8);
                uint32_t b[4][2];
                #pragma unroll
                for (int nt = 0; nt < 4; ++nt) {
                    const uint2 bv = __ldg((const uint2*)(wB + (oc0 + nt * 8 + g) * 8 + 2 * tig));
                    b[nt][0] = bv.x;
                    b[nt][1] = bv.y;
                }
                #pragma unroll
                for (int mt = 0; mt < 4; ++mt) {
                    const uint32_t* ab = rowA + cb64 + mt * 16 + g + kw;
                    uint32_t a0 = ab[tig * CSTR];
                    uint32_t a1 = ab[tig * CSTR + 8];
                    uint32_t a2 = ab[(tig + 4) * CSTR];
                    uint32_t a3 = ab[(tig + 4) * CSTR + 8];
                    #pragma unroll
                    for (int nt = 0; nt < 4; ++nt)
                        asm volatile(
                            "mma.sync.aligned.m16n8k16.row.col.f32.f16.f16.f32 "
                            "{%0,%1,%2,%3}, {%4,%5,%6,%7}, {%8,%9}, {%0,%1,%2,%3};"
                            : "+f"(c[mt][nt][0]), "+f"(c[mt][nt][1]),
                              "+f"(c[mt][nt][2]), "+f"(c[mt][nt][3])
                            : "r"(a0), "r"(a1), "r"(a2), "r"(a3),
                              "r"(b[nt][0]), "r"(b[nt][1]));
                }
            }
        }

        // ---- overlap: stage next chunk into the other buffer ----
        if (chunk < 3) stage(chunk + 1, sIn + ((chunk + 1) & 1) * SIN_BUF);
        __syncthreads();
    }

    // ---- epilogue: bias + store ----
    const int h = h0 + r_out;
    #pragma unroll
    for (int mt = 0; mt < 4; ++mt) {
        const int px = w0 + cb64 + mt * 16 + g;
        #pragma unroll
        for (int nt = 0; nt < 4; ++nt) {
            const int oc = oc0 + nt * 8 + 2 * tig;
            const size_t b0 = (((size_t)n * 64 + oc) * 256 + h) * 256;
            const size_t b1 = (((size_t)n * 64 + oc + 1) * 256 + h) * 256;
            out[b0 + px]     = c[mt][nt][0] + sB[oc];
            out[b1 + px]     = c[mt][nt][1] + sB[oc + 1];
            out[b0 + px + 8] = c[mt][nt][2] + sB[oc];
            out[b1 + px + 8] = c[mt][nt][3] + sB[oc + 1];
        }
    }
}

extern "C" void kernel_launch(void* const* d_in, const int* in_sizes, int n_in,
                              void* d_out, int out_size)
{
    const float* x  = (const float*)d_in[0];
    const float* Wt = (const float*)d_in[1];
    const float* b  = (const float*)d_in[2];
    float* out = (float*)d_out;

    cudaFuncSetAttribute(conv_f16_mma_kernel,
                         cudaFuncAttributeMaxDynamicSharedMemorySize, SMEM_BYTES);

    prep_weights<<<72, 256>>>(Wt);

    dim3 grid(2, 128, 16);   // (w-half, h-pair, n): 4096 CTAs, 2x128 px x 64 oc
    conv_f16_mma_kernel<<<grid, 256, SMEM_BYTES>>>(x, b, out);
}

// round 8
// speedup vs baseline: 1.4121x; 1.1112x over previous
#include <cuda_runtime.h>
#include <cuda_fp16.h>
#include <cstdint>

// ============================ weight prep =====================================
// g_W3[chunk][tap][oc][psi] : half2 = (W[ic0+2p], W[ic0+2p+1]), psi(p)=(p&3)*2+(p>>2)
// LDS.64 at u32 offset 2*tig yields pairs {tig, tig+4} = (b0, b1) of m16n8k16.
__device__ uint32_t g_W3[4 * 9 * 64 * 8];

__global__ void prep_weights(const float* __restrict__ Wt) {
    int i = blockIdx.x * 256 + threadIdx.x;   // 18432 total
    if (i >= 4 * 9 * 64 * 8) return;
    int q     = i & 7;
    int oc    = (i >> 3) & 63;
    int tap   = (i >> 9) % 9;
    int chunk = i / (512 * 9);
    int p     = (q >> 1) + (q & 1) * 4;       // inverse psi
    int kh    = tap / 3;
    int kw    = tap % 3;
    int ic    = chunk * 16 + 2 * p;
    float w0 = Wt[((oc * 64 + ic) * 3 + kh) * 3 + kw];
    float w1 = Wt[((oc * 64 + ic + 1) * 3 + kh) * 3 + kw];
    __half2 hv = __floats2half2_rn(w0, w1);
    g_W3[i] = *(uint32_t*)&hv;
}

// SMEM (u32): sW[4][9][64][8] = 18432, sIn[2 buf][6 r][8 p][72] = 6912, bias 64
#define COLS 66
#define CSTR 72
#define SIN_BUF (6 * 8 * CSTR)                    // 3456 u32 per buffer
#define SW_ALL  (4 * 9 * 64 * 8)                  // 18432 u32
#define SMEM_BYTES ((SW_ALL + 2 * SIN_BUF + 64) * 4)

__global__ __launch_bounds__(256, 2)
void conv_f16_mma_kernel(const float* __restrict__ x,
                         const float* __restrict__ bias,
                         float* __restrict__ out)
{
    extern __shared__ uint32_t sm[];
    uint32_t* sW  = sm;                            // all 4 chunks of weights
    uint32_t* sIn = sm + SW_ALL;                   // [buf][r][p][col]
    float*    sB  = (float*)(sm + SW_ALL + 2 * SIN_BUF);

    const int tid  = threadIdx.x;
    const int lane = tid & 31;
    const int wid  = tid >> 5;
    const int g    = lane >> 2;
    const int tig  = lane & 3;
    const int w0   = blockIdx.x * 64;              // w-quarter
    const int h0   = blockIdx.y * 4;               // h-quad
    const int n    = blockIdx.z;

    // 8 warps: r_out(4) x oc-half(2); each warp 64 px x 32 oc
    const int r_out = wid >> 1;
    const int oc0   = 32 * (wid & 1);

    // ---- one-time: stage all weights (73.7 KB) + bias ----
    {
        const uint4* srcW = (const uint4*)g_W3;
        uint4* dstW = (uint4*)sW;
        #pragma unroll
        for (int i = 0; i < SW_ALL / 4 / 256; ++i)   // 18 iterations
            dstW[tid + i * 256] = srcW[tid + i * 256];
        if (tid < 64) sB[tid] = bias[tid];
    }

    float c[4][4][4];
    #pragma unroll
    for (int mt = 0; mt < 4; ++mt)
        #pragma unroll
        for (int nt = 0; nt < 4; ++nt)
            #pragma unroll
            for (int r = 0; r < 4; ++r) c[mt][nt][r] = 0.0f;

    // ---- staging: 6 rows x 8 ic-pairs x 66 cols as half2 ----
    auto stage = [&](int chunk, uint32_t* dst) {
        const int ic0 = chunk * 16;
        for (int i = tid; i < 6 * 8 * COLS; i += 256) {
            int col = i % COLS;                     // coalesced across lanes
            int t2  = i / COLS;
            int p   = t2 & 7;
            int r   = t2 >> 3;
            int gh  = h0 - 1 + r;
            int gw  = w0 - 1 + col;
            float v0 = 0.0f, v1 = 0.0f;
            if ((unsigned)gh < 256u && (unsigned)gw < 256u) {
                const float* base = x + (((size_t)n * 64 + ic0 + 2 * p) * 256 + gh) * 256 + gw;
                v0 = __ldg(base);
                v1 = __ldg(base + 256 * 256);
            }
            __half2 hv = __floats2half2_rn(v0, v1);
            dst[(r * 8 + p) * CSTR + col] = *(uint32_t*)&hv;
        }
    };

    stage(0, sIn);
    __syncthreads();

    for (int chunk = 0; chunk < 4; ++chunk) {
        const uint32_t* buf = sIn + (chunk & 1) * SIN_BUF;
        const uint32_t* wC  = sW + chunk * (9 * 64 * 8);

        // ---- compute: 9 taps x (4 mt x 4 nt) m16n8k16 ----
        #pragma unroll
        for (int kh = 0; kh < 3; ++kh) {
            const uint32_t* rowA = buf + (r_out + kh) * (8 * CSTR);
            #pragma unroll
            for (int kw = 0; kw < 3; ++kw) {
                const uint32_t* wB = wC + (kh * 3 + kw) * (64 * 8);
                uint32_t b[4][2];
                #pragma unroll
                for (int nt = 0; nt < 4; ++nt) {
                    const uint2 bv = *(const uint2*)(wB + (oc0 + nt * 8 + g) * 8 + 2 * tig);
                    b[nt][0] = bv.x;
                    b[nt][1] = bv.y;
                }
                #pragma unroll
                for (int mt = 0; mt < 4; ++mt) {
                    const uint32_t* ab = rowA + mt * 16 + g + kw;
                    uint32_t a0 = ab[tig * CSTR];
                    uint32_t a1 = ab[tig * CSTR + 8];
                    uint32_t a2 = ab[(tig + 4) * CSTR];
                    uint32_t a3 = ab[(tig + 4) * CSTR + 8];
                    #pragma unroll
                    for (int nt = 0; nt < 4; ++nt)
                        asm volatile(
                            "mma.sync.aligned.m16n8k16.row.col.f32.f16.f16.f32 "
                            "{%0,%1,%2,%3}, {%4,%5,%6,%7}, {%8,%9}, {%0,%1,%2,%3};"
                            : "+f"(c[mt][nt][0]), "+f"(c[mt][nt][1]),
                              "+f"(c[mt][nt][2]), "+f"(c[mt][nt][3])
                            : "r"(a0), "r"(a1), "r"(a2), "r"(a3),
                              "r"(b[nt][0]), "r"(b[nt][1]));
                }
            }
        }

        // ---- overlap: stage next chunk into the other buffer ----
        if (chunk < 3) stage(chunk + 1, sIn + ((chunk + 1) & 1) * SIN_BUF);
        __syncthreads();
    }

    // ---- epilogue: bias + store ----
    const int h = h0 + r_out;
    #pragma unroll
    for (int mt = 0; mt < 4; ++mt) {
        const int px = w0 + mt * 16 + g;
        #pragma unroll
        for (int nt = 0; nt < 4; ++nt) {
            const int oc = oc0 + nt * 8 + 2 * tig;
            const size_t b0 = (((size_t)n * 64 + oc) * 256 + h) * 256;
            const size_t b1 = (((size_t)n * 64 + oc + 1) * 256 + h) * 256;
            out[b0 + px]     = c[mt][nt][0] + sB[oc];
            out[b1 + px]     = c[mt][nt][1] + sB[oc + 1];
            out[b0 + px + 8] = c[mt][nt][2] + sB[oc];
            out[b1 + px + 8] = c[mt][nt][3] + sB[oc + 1];
        }
    }
}

extern "C" void kernel_launch(void* const* d_in, const int* in_sizes, int n_in,
                              void* d_out, int out_size)
{
    const float* x  = (const float*)d_in[0];
    const float* Wt = (const float*)d_in[1];
    const float* b  = (const float*)d_in[2];
    float* out = (float*)d_out;

    cudaFuncSetAttribute(conv_f16_mma_kernel,
                         cudaFuncAttributeMaxDynamicSharedMemorySize, SMEM_BYTES);

    prep_weights<<<72, 256>>>(Wt);

    dim3 grid(4, 64, 16);   // (w-quarter, h-quad, n): 4096 CTAs, 4x64 px x 64 oc
    conv_f16_mma_kernel<<<grid, 256, SMEM_BYTES>>>(x, b, out);
}

// round 9
// speedup vs baseline: 1.7580x; 1.2449x over previous
#include <cuda_runtime.h>
#include <cuda_fp16.h>
#include <cstdint>

__device__ __forceinline__ uint32_t smem_u32(const void* p) {
    uint32_t a;
    asm("{ .reg .u64 t; cvta.to.shared.u64 t, %1; cvt.u32.u64 %0, t; }" : "=r"(a) : "l"(p));
    return a;
}

// ============================ weight prep =====================================
// g_W3[chunk][tap][oc][psi] : half2 = (W[ic0+2p], W[ic0+2p+1]), psi(p)=(p&3)*2+(p>>2)
// LDS.64 at u32 offset 2*tig yields pairs {tig, tig+4} = (b0, b1) of m16n8k16.
__device__ uint32_t g_W3[4 * 9 * 64 * 8];

__global__ void prep_weights(const float* __restrict__ Wt) {
    int i = blockIdx.x * 256 + threadIdx.x;   // 18432 total
    if (i >= 4 * 9 * 64 * 8) return;
    int q     = i & 7;
    int oc    = (i >> 3) & 63;
    int tap   = (i >> 9) % 9;
    int chunk = i / (512 * 9);
    int p     = (q >> 1) + (q & 1) * 4;       // inverse psi
    int kh    = tap / 3;
    int kw    = tap % 3;
    int ic    = chunk * 16 + 2 * p;
    float w0 = Wt[((oc * 64 + ic) * 3 + kh) * 3 + kw];
    float w1 = Wt[((oc * 64 + ic + 1) * 3 + kh) * 3 + kw];
    __half2 hv = __floats2half2_rn(w0, w1);
    g_W3[i] = *(uint32_t*)&hv;
}

// SMEM (u32): sW[4][9][64][8]=18432, sIn[2][6r][2ph][66col][4]=2*3168, bias 64
#define COLS 66
#define SIN_BUF (6 * 2 * COLS * 4)               // 3168 u32 per buffer
#define SW_ALL  (4 * 9 * 64 * 8)
#define SMEM_BYTES ((SW_ALL + 2 * SIN_BUF + 64) * 4)

__global__ __launch_bounds__(256, 2)
void conv_f16_mma_kernel(const float* __restrict__ x,
                         const float* __restrict__ bias,
                         float* __restrict__ out)
{
    extern __shared__ uint32_t sm[];
    uint32_t* sW  = sm;
    uint32_t* sIn = sm + SW_ALL;                  // [buf][r][ph][col][4]
    float*    sB  = (float*)(sm + SW_ALL + 2 * SIN_BUF);
    const uint32_t sInAddr = smem_u32(sIn);

    const int tid  = threadIdx.x;
    const int lane = tid & 31;
    const int wid  = tid >> 5;
    const int g    = lane >> 2;
    const int tig  = lane & 3;
    const int w0   = blockIdx.x * 64;
    const int h0   = blockIdx.y * 4;
    const int n    = blockIdx.z;

    // 8 warps: r_out(4) x oc-half(2); each warp 64 px x 32 oc
    const int r_out = wid >> 1;
    const int oc0   = 32 * (wid & 1);

    // ldmatrix per-lane address pieces: matrix row + k-half select
    const int m_lane = (lane & 7) + 8 * ((lane >> 3) & 1);
    const int ph_l   = lane >> 4;
    const uint32_t laneOff = (uint32_t)(ph_l * COLS + m_lane) * 16u;

    // ---- one-time: stage all weights + bias ----
    {
        const uint4* srcW = (const uint4*)g_W3;
        uint4* dstW = (uint4*)sW;
        #pragma unroll
        for (int i = 0; i < SW_ALL / 4 / 256; ++i)
            dstW[tid + i * 256] = srcW[tid + i * 256];
        if (tid < 64) sB[tid] = bias[tid];
    }

    float c[4][4][4];
    #pragma unroll
    for (int mt = 0; mt < 4; ++mt)
        #pragma unroll
        for (int nt = 0; nt < 4; ++nt)
            #pragma unroll
            for (int r = 0; r < 4; ++r) c[mt][nt][r] = 0.0f;

    // ---- staging: 12 (r,ph) x 66 cols; one uint4 (8 k-halves) per iter ----
    auto stage = [&](int chunk, uint32_t* dst) {
        for (int i = tid; i < 12 * COLS; i += 256) {
            int col = i % COLS;                    // coalesced across lanes
            int t2  = i / COLS;                    // r*2 + ph
            int r   = t2 >> 1;
            int ph  = t2 & 1;
            int gh  = h0 - 1 + r;
            int gw  = w0 - 1 + col;
            uint4 v = make_uint4(0u, 0u, 0u, 0u);
            if ((unsigned)gh < 256u && (unsigned)gw < 256u) {
                const int icb = chunk * 16 + ph * 8;
                const float* base = x + (((size_t)n * 64 + icb) * 256 + gh) * 256 + gw;
                const int S = 256 * 256;
                __half2 h0v = __floats2half2_rn(__ldg(base),         __ldg(base + S));
                __half2 h1v = __floats2half2_rn(__ldg(base + 2 * S), __ldg(base + 3 * S));
                __half2 h2v = __floats2half2_rn(__ldg(base + 4 * S), __ldg(base + 5 * S));
                __half2 h3v = __floats2half2_rn(__ldg(base + 6 * S), __ldg(base + 7 * S));
                v.x = *(uint32_t*)&h0v;
                v.y = *(uint32_t*)&h1v;
                v.z = *(uint32_t*)&h2v;
                v.w = *(uint32_t*)&h3v;
            }
            *(uint4*)(dst + (size_t)i * 4) = v;    // STS.128, conflict-free
        }
    };

    stage(0, sIn);
    __syncthreads();

    for (int chunk = 0; chunk < 4; ++chunk) {
        const uint32_t bufAddr = sInAddr + (uint32_t)((chunk & 1) * SIN_BUF) * 4u;
        const uint32_t* wC = sW + chunk * (9 * 64 * 8);

        // ---- compute: 9 taps; A via ldmatrix.x4, B via LDS.64 ----
        #pragma unroll
        for (int kh = 0; kh < 3; ++kh) {
            const uint32_t rowAddr = bufAddr
                + (uint32_t)((r_out + kh) * 2 * COLS) * 16u + laneOff;
            #pragma unroll
            for (int kw = 0; kw < 3; ++kw) {
                const uint32_t* wB = wC + (kh * 3 + kw) * (64 * 8);
                uint32_t b[4][2];
                #pragma unroll
                for (int nt = 0; nt < 4; ++nt) {
                    const uint2 bv = *(const uint2*)(wB + (oc0 + nt * 8 + g) * 8 + 2 * tig);
                    b[nt][0] = bv.x;
                    b[nt][1] = bv.y;
                }
                const uint32_t aCol = rowAddr + (uint32_t)kw * 16u;
                #pragma unroll
                for (int mt = 0; mt < 4; ++mt) {
                    uint32_t a0, a1, a2, a3;
                    asm volatile(
                        "ldmatrix.sync.aligned.m8n8.x4.shared.b16 {%0,%1,%2,%3}, [%4];"
                        : "=r"(a0), "=r"(a1), "=r"(a2), "=r"(a3)
                        : "r"(aCol + (uint32_t)(mt * 16) * 16u));
                    #pragma unroll
                    for (int nt = 0; nt < 4; ++nt)
                        asm volatile(
                            "mma.sync.aligned.m16n8k16.row.col.f32.f16.f16.f32 "
                            "{%0,%1,%2,%3}, {%4,%5,%6,%7}, {%8,%9}, {%0,%1,%2,%3};"
                            : "+f"(c[mt][nt][0]), "+f"(c[mt][nt][1]),
                              "+f"(c[mt][nt][2]), "+f"(c[mt][nt][3])
                            : "r"(a0), "r"(a1), "r"(a2), "r"(a3),
                              "r"(b[nt][0]), "r"(b[nt][1]));
                }
            }
        }

        // ---- overlap: stage next chunk into the other buffer ----
        if (chunk < 3) stage(chunk + 1, sIn + ((chunk + 1) & 1) * SIN_BUF);
        __syncthreads();
    }

    // ---- epilogue: bias + store ----
    const int h = h0 + r_out;
    #pragma unroll
    for (int mt = 0; mt < 4; ++mt) {
        const int px = w0 + mt * 16 + g;
        #pragma unroll
        for (int nt = 0; nt < 4; ++nt) {
            const int oc = oc0 + nt * 8 + 2 * tig;
            const size_t b0 = (((size_t)n * 64 + oc) * 256 + h) * 256;
            const size_t b1 = (((size_t)n * 64 + oc + 1) * 256 + h) * 256;
            out[b0 + px]     = c[mt][nt][0] + sB[oc];
            out[b1 + px]     = c[mt][nt][1] + sB[oc + 1];
            out[b0 + px + 8] = c[mt][nt][2] + sB[oc];
            out[b1 + px + 8] = c[mt][nt][3] + sB[oc + 1];
        }
    }
}

extern "C" void kernel_launch(void* const* d_in, const int* in_sizes, int n_in,
                              void* d_out, int out_size)
{
    const float* x  = (const float*)d_in[0];
    const float* Wt = (const float*)d_in[1];
    const float* b  = (const float*)d_in[2];
    float* out = (float*)d_out;

    cudaFuncSetAttribute(conv_f16_mma_kernel,
                         cudaFuncAttributeMaxDynamicSharedMemorySize, SMEM_BYTES);

    prep_weights<<<72, 256>>>(Wt);

    dim3 grid(4, 64, 16);   // (w-quarter, h-quad, n): 4096 CTAs, 4x64 px x 64 oc
    conv_f16_mma_kernel<<<grid, 256, SMEM_BYTES>>>(x, b, out);
}